// round 8
// baseline (speedup 1.0000x reference)
#include <cuda_runtime.h>

// Problem constants
#define B_   64
#define C_   256
#define HW_  4096
#define EMB_ 512
#define BT   2                              // batches per stage1 warp-task
#define NTASK (C_ * (B_ / BT))              // 8192 stage1 tasks
#define STG_BLOCKS (NTASK / 8)              // 1024 blocks x 8 warps
#define W3_TILE 4
#define W3_BLOCKS (C_ / W3_TILE)            // 64 blocks

// Scratch (allocation-free rule: __device__ globals)
__device__ float g_t1[B_ * C_];   // t1[b] = kv_w_v @ ce[b] + kv_b_v
__device__ float g_W3[C_ * C_];   // W3 = out_w @ wv
__device__ float g_d3[C_];        // d3 = out_w @ bv + out_b

// ---------------------------------------------------------------------------
// Launch 1: two independent roles in one kernel.
//  bid <  W3_BLOCKS : W3 rows [bid*4, bid*4+4) + d3 for those rows.
//  bid >= W3_BLOCKS : stage1 tasks (one warp per (row, batch-pair)).
// The roles have no dependency, so they just pack the chip together.
// ---------------------------------------------------------------------------
__global__ void __launch_bounds__(256) pre_kernel(
    const float* __restrict__ cond_emb,    // (B, EMB)
    const float* __restrict__ in_proj_w,   // (3C, C): wv = rows [2C,3C)
    const float* __restrict__ in_proj_b,   // (3C,):   bv = [2C,3C)
    const float* __restrict__ out_w,       // (C, C)
    const float* __restrict__ out_b,       // (C,)
    const float* __restrict__ kv_w,        // (2C, EMB): v-part = rows [C,2C)
    const float* __restrict__ kv_b)        // (2C,)
{
    const int bid  = blockIdx.x;
    const int tid  = threadIdx.x;
    const int lane = tid & 31;
    const int warp = tid >> 5;

    if (bid < W3_BLOCKS) {
        // ---- W3[r0+j][tid] = sum_i out_w[r0+j][i] * wv[i][tid] ----
        const int r0 = bid * W3_TILE;
        const float* __restrict__ wv = in_proj_w + (size_t)2 * C_ * C_;
        const float* __restrict__ bv = in_proj_b + 2 * C_;

        float acc0 = 0.f, acc1 = 0.f, acc2 = 0.f, acc3 = 0.f;
        #pragma unroll 16
        for (int i = 0; i < C_; i++) {
            const float wvv = wv[(size_t)i * C_ + tid];     // coalesced
            acc0 += out_w[(size_t)(r0 + 0) * C_ + i] * wvv; // uniform bcast
            acc1 += out_w[(size_t)(r0 + 1) * C_ + i] * wvv;
            acc2 += out_w[(size_t)(r0 + 2) * C_ + i] * wvv;
            acc3 += out_w[(size_t)(r0 + 3) * C_ + i] * wvv;
        }
        g_W3[(size_t)(r0 + 0) * C_ + tid] = acc0;
        g_W3[(size_t)(r0 + 1) * C_ + tid] = acc1;
        g_W3[(size_t)(r0 + 2) * C_ + tid] = acc2;
        g_W3[(size_t)(r0 + 3) * C_ + tid] = acc3;

        // ---- d3[r0+j] = dot(out_w[r0+j], bv) + out_b[r0+j] ----
        __shared__ float s_part[8];
        const float bvv = bv[tid];
        #pragma unroll
        for (int j = 0; j < W3_TILE; j++) {
            float p = out_w[(size_t)(r0 + j) * C_ + tid] * bvv;
            #pragma unroll
            for (int o = 16; o > 0; o >>= 1)
                p += __shfl_down_sync(0xffffffffu, p, o);
            if (lane == 0) s_part[warp] = p;
            __syncthreads();
            if (tid == 0) {
                float q = 0.f;
                #pragma unroll
                for (int w = 0; w < 8; w++) q += s_part[w];
                g_d3[r0 + j] = q + out_b[r0 + j];
            }
            __syncthreads();
        }
    } else {
        // ---- stage1: t1[(b0+j)][r] = dot(kv_w_v[r], ce[b0+j]) + kv_b_v[r] ----
        const int gw = (bid - W3_BLOCKS) * 8 + warp;   // 0 .. NTASK-1
        const int r  = gw & (C_ - 1);
        const int b0 = (gw >> 8) * BT;

        const float4* __restrict__ wrow =
            reinterpret_cast<const float4*>(kv_w + (size_t)(C_ + r) * EMB_);
        const float4* __restrict__ xin =
            reinterpret_cast<const float4*>(cond_emb + (size_t)b0 * EMB_);

        float acc0 = 0.f, acc1 = 0.f;
        #pragma unroll
        for (int k = lane; k < EMB_ / 4; k += 32) {
            const float4 a  = wrow[k];
            const float4 c0 = xin[k];
            const float4 c1 = xin[(EMB_ / 4) + k];
            acc0 += a.x * c0.x + a.y * c0.y + a.z * c0.z + a.w * c0.w;
            acc1 += a.x * c1.x + a.y * c1.y + a.z * c1.z + a.w * c1.w;
        }
        #pragma unroll
        for (int o = 16; o > 0; o >>= 1) {
            acc0 += __shfl_down_sync(0xffffffffu, acc0, o);
            acc1 += __shfl_down_sync(0xffffffffu, acc1, o);
        }
        if (lane == 0) {
            const float bs = kv_b[C_ + r];
            g_t1[(size_t)b0 * C_ + r]       = acc0 + bs;
            g_t1[(size_t)(b0 + 1) * C_ + r] = acc1 + bs;
        }
    }
}

// ---------------------------------------------------------------------------
// Launch 2: stream kernel with inline final projection:
//   a       = dot(W3[c,:], t1[b,:]) + d3[c]
//   y[bc,:] = x[bc,:] + a
// Dot reads are 2KB L2-resident per block, hidden under 4 in-flight x loads.
// ---------------------------------------------------------------------------
__global__ void __launch_bounds__(256) broadcast_add_kernel(
    const float* __restrict__ x,
    float* __restrict__ y)
{
    const int bc   = blockIdx.x;                 // 0 .. B*C-1
    const int b    = bc >> 8;
    const int c    = bc & (C_ - 1);
    const int tid  = threadIdx.x;
    const int lane = tid & 31;
    const int warp = tid >> 5;

    const float4* __restrict__ xi = reinterpret_cast<const float4*>(x) + (size_t)bc * (HW_ / 4);
    float4* __restrict__       yo = reinterpret_cast<float4*>(y)       + (size_t)bc * (HW_ / 4);

    // Streaming loads first; the dot hides beneath them.
    float4 v0 = xi[tid];
    float4 v1 = xi[tid + 256];
    float4 v2 = xi[tid + 512];
    float4 v3 = xi[tid + 768];

    float p = g_W3[(size_t)c * C_ + tid] * g_t1[(size_t)b * C_ + tid];
    #pragma unroll
    for (int o = 16; o > 0; o >>= 1)
        p += __shfl_down_sync(0xffffffffu, p, o);

    __shared__ float s_part[8];
    __shared__ float s_a;
    if (lane == 0) s_part[warp] = p;
    __syncthreads();
    if (tid < 8) {
        float q = s_part[tid];
        q += __shfl_down_sync(0x000000ffu, q, 4);
        q += __shfl_down_sync(0x000000ffu, q, 2);
        q += __shfl_down_sync(0x000000ffu, q, 1);
        if (tid == 0) s_a = q + g_d3[c];
    }
    __syncthreads();
    const float a = s_a;

    v0.x += a; v0.y += a; v0.z += a; v0.w += a;
    v1.x += a; v1.y += a; v1.z += a; v1.w += a;
    v2.x += a; v2.y += a; v2.z += a; v2.w += a;
    v3.x += a; v3.y += a; v3.z += a; v3.w += a;
    yo[tid]       = v0;
    yo[tid + 256] = v1;
    yo[tid + 512] = v2;
    yo[tid + 768] = v3;
}

extern "C" void kernel_launch(void* const* d_in, const int* in_sizes, int n_in,
                              void* d_out, int out_size)
{
    // metadata order: x, cond_emb, ln_gamma, ln_beta, in_proj_w, in_proj_b,
    //                 out_w, out_b, kv_w, kv_b
    const float* x         = (const float*)d_in[0];
    const float* cond_emb  = (const float*)d_in[1];
    // ln_gamma/ln_beta provably do not affect the output: softmax over the
    // size-1 KV axis is exactly 1, so q (and thus x_ln) cancels.
    const float* in_proj_w = (const float*)d_in[4];
    const float* in_proj_b = (const float*)d_in[5];
    const float* out_w     = (const float*)d_in[6];
    const float* out_b     = (const float*)d_in[7];
    const float* kv_w      = (const float*)d_in[8];
    const float* kv_b      = (const float*)d_in[9];
    float* y = (float*)d_out;

    pre_kernel<<<W3_BLOCKS + STG_BLOCKS, 256>>>(cond_emb, in_proj_w, in_proj_b,
                                                out_w, out_b, kv_w, kv_b);
    broadcast_add_kernel<<<B_ * C_, 256>>>(x, y);
}

// round 10
// speedup vs baseline: 1.4775x; 1.4775x over previous
#include <cuda_runtime.h>

// Problem constants
#define B_   64
#define C_   256
#define HW_  4096
#define EMB_ 512
#define NTASK (B_ * C_)        // 16384 outputs per stage, one warp each
#define STG_BLOCKS (NTASK / 8) // 2048 blocks x 8 warps

// Scratch (allocation-free rule: __device__ globals)
__device__ float g_t1[B_ * C_];
__device__ float g_t2[B_ * C_];

// ---------------------------------------------------------------------------
// Stage: out[b*C + r] = dot(W[r], in[b], LEN) + bias[r].
// One warp per output (max parallelism — these stages are L2-latency bound,
// occupancy is the lever, not traffic). float4 loads, unrolled.
// ---------------------------------------------------------------------------
template <int LEN>
__global__ void __launch_bounds__(256) stage_kernel(
    const float* __restrict__ W,      // (C_, LEN) row-major (pre-offset)
    const float* __restrict__ invec,  // (B_, LEN)
    const float* __restrict__ bias,   // (C_,) pre-offset
    float* __restrict__ out)          // (B_, C_)
{
    const int lane = threadIdx.x & 31;
    const int gw   = blockIdx.x * 8 + (threadIdx.x >> 5);   // 0 .. NTASK-1
    const int r    = gw & (C_ - 1);
    const int b    = gw >> 8;

    const float4* __restrict__ wrow = reinterpret_cast<const float4*>(W + (size_t)r * LEN);
    const float4* __restrict__ xin  = reinterpret_cast<const float4*>(invec + (size_t)b * LEN);

    float acc = 0.f;
    #pragma unroll
    for (int k = lane; k < LEN / 4; k += 32) {
        const float4 a = wrow[k];
        const float4 c = xin[k];
        acc += a.x * c.x + a.y * c.y + a.z * c.z + a.w * c.w;
    }
    #pragma unroll
    for (int o = 16; o > 0; o >>= 1)
        acc += __shfl_down_sync(0xffffffffu, acc, o);
    if (lane == 0)
        out[(size_t)b * C_ + r] = acc + bias[r];
}

// ---------------------------------------------------------------------------
// Stream kernel with SYNC-FREE inline stage 3:
//   a       = dot(out_w[c,:], t2[b,:]) + out_b[c]
//   y[bc,:] = x[bc,:] + a
// Every warp computes the full 256-dot redundantly (2 float4 loads each of
// out_w-row and t2-row per lane, warp shuffle reduce, broadcast via shfl).
// No __syncthreads, no shared memory on the load->store critical path.
// ---------------------------------------------------------------------------
__global__ void __launch_bounds__(256) broadcast_add_kernel(
    const float* __restrict__ x,
    const float* __restrict__ out_w,   // (C_, C_)
    const float* __restrict__ out_b,   // (C_,)
    float* __restrict__ y)
{
    const int bc   = blockIdx.x;                 // 0 .. B*C-1
    const int b    = bc >> 8;
    const int c    = bc & (C_ - 1);
    const int tid  = threadIdx.x;
    const int lane = tid & 31;

    const float4* __restrict__ xi = reinterpret_cast<const float4*>(x) + (size_t)bc * (HW_ / 4);
    float4* __restrict__       yo = reinterpret_cast<float4*>(y)       + (size_t)bc * (HW_ / 4);

    // Streaming loads first; the dot hides beneath them.
    float4 v0 = xi[tid];
    float4 v1 = xi[tid + 256];
    float4 v2 = xi[tid + 512];
    float4 v3 = xi[tid + 768];

    // Per-warp redundant 256-dot (L1-broadcast across the 8 warps).
    const float4* __restrict__ wr = reinterpret_cast<const float4*>(out_w + (size_t)c * C_);
    const float4* __restrict__ tr = reinterpret_cast<const float4*>(g_t2 + (size_t)b * C_);
    const float4 w0 = wr[lane],       t0 = tr[lane];
    const float4 w1 = wr[lane + 32],  t1 = tr[lane + 32];
    float p = w0.x * t0.x + w0.y * t0.y + w0.z * t0.z + w0.w * t0.w
            + w1.x * t1.x + w1.y * t1.y + w1.z * t1.z + w1.w * t1.w;
    #pragma unroll
    for (int o = 16; o > 0; o >>= 1)
        p += __shfl_xor_sync(0xffffffffu, p, o);   // butterfly: all lanes hold sum
    const float a = p + out_b[c];

    v0.x += a; v0.y += a; v0.z += a; v0.w += a;
    v1.x += a; v1.y += a; v1.z += a; v1.w += a;
    v2.x += a; v2.y += a; v2.z += a; v2.w += a;
    v3.x += a; v3.y += a; v3.z += a; v3.w += a;
    yo[tid]       = v0;
    yo[tid + 256] = v1;
    yo[tid + 512] = v2;
    yo[tid + 768] = v3;
}

extern "C" void kernel_launch(void* const* d_in, const int* in_sizes, int n_in,
                              void* d_out, int out_size)
{
    // metadata order: x, cond_emb, ln_gamma, ln_beta, in_proj_w, in_proj_b,
    //                 out_w, out_b, kv_w, kv_b
    const float* x         = (const float*)d_in[0];
    const float* cond_emb  = (const float*)d_in[1];
    // ln_gamma/ln_beta provably do not affect the output: softmax over the
    // size-1 KV axis is exactly 1, so q (and thus x_ln) cancels.
    const float* in_proj_w = (const float*)d_in[4];
    const float* in_proj_b = (const float*)d_in[5];
    const float* out_w     = (const float*)d_in[6];
    const float* out_b     = (const float*)d_in[7];
    const float* kv_w      = (const float*)d_in[8];
    const float* kv_b      = (const float*)d_in[9];
    float* y = (float*)d_out;

    float *t1, *t2;
    cudaGetSymbolAddress((void**)&t1, g_t1);
    cudaGetSymbolAddress((void**)&t2, g_t2);

    // Stage 1: t1[b] = kv_w[C:2C] @ ce[b] + kv_b[C:]
    stage_kernel<EMB_><<<STG_BLOCKS, 256>>>(kv_w + (size_t)C_ * EMB_, cond_emb,
                                            kv_b + C_, t1);
    // Stage 2: t2[b] = wv @ t1[b] + bv
    stage_kernel<C_><<<STG_BLOCKS, 256>>>(in_proj_w + (size_t)2 * C_ * C_, t1,
                                          in_proj_b + 2 * C_, t2);
    // Stage 3 fused (sync-free) into the stream kernel.
    broadcast_add_kernel<<<B_ * C_, 256>>>(x, out_w, out_b, y);
}